// round 1
// baseline (speedup 1.0000x reference)
#include <cuda_runtime.h>
#include <cuda_bf16.h>
#include <cstddef>

// Problem constants
#define NB 4          // batch
#define NT 4096       // tokens (q and kv)
#define ND 1024       // d_model
#define NH 16         // heads
#define NE 64         // head_dim
#define NBH (NB*NH)   // 64
#define NM (NB*NT)    // 16384 rows of the big GEMMs
#define SPLIT 8
#define TCH (NT/SPLIT) // 512

// ---------------- scratch (device globals; no allocations allowed) ----------
__device__ float g_Wt[3][ND*ND];        // transposed proj weights (q,k,v): [K][N]
__device__ float g_Wot[ND*ND];          // Wo^T as [K][N]
__device__ float g_feat[3][(size_t)NBH*NT*NE]; // qh2, kh2, vh in [b,h,t,e]
__device__ float g_attn[(size_t)NM*ND];        // attn in [b,t,(h,e)]
__device__ float g_kvpart[(size_t)NBH*SPLIT*NE*NE];
__device__ float g_kspart[(size_t)NBH*SPLIT*NE];
__device__ float g_kvsum[(size_t)NBH*NE*NE];
__device__ float g_ksum[(size_t)NBH*NE];

// ---------------- weight transposes ----------------------------------------
// Wt[k][h*64+e] = W[h][k][e]
__global__ void transpose_proj_w(const float* __restrict__ W, float* __restrict__ Wt) {
    int idx = blockIdx.x * blockDim.x + threadIdx.x;
    if (idx >= ND*ND) return;
    int k = idx / ND, n = idx % ND;
    int h = n >> 6, e = n & 63;
    Wt[idx] = W[((size_t)h*ND + k)*NE + e];
}
// Wot[k][n] = Wo[n][k]
__global__ void transpose_wo(const float* __restrict__ Wo, float* __restrict__ Wot) {
    int idx = blockIdx.x * blockDim.x + threadIdx.x;
    if (idx >= ND*ND) return;
    int k = idx / ND, n = idx % ND;
    Wot[idx] = Wo[(size_t)n*ND + k];
}

// ---------------- SGEMM: C = A[MxK] * B[KxN] + bias[n], optional square -----
// MODE 0: plain row-major output (final GEMM)
// MODE 1: proj output layout [b,h,t,e], square epilogue (q,k)
// MODE 2: proj output layout [b,h,t,e], no square (v)
template<int MODE>
__global__ __launch_bounds__(256) void sgemm128(
    const float* __restrict__ A, const float* __restrict__ Bm,
    const float* __restrict__ bias, float* __restrict__ C,
    int M, int N, int K)
{
    __shared__ float As[8][128];
    __shared__ float Bs[8][128];
    const int tid = threadIdx.x;
    const int m0 = blockIdx.y * 128;
    const int n0 = blockIdx.x * 128;

    const int aRow = tid >> 1;            // 0..127
    const int aCol = (tid & 1) << 2;      // 0 or 4
    const int bRow = tid >> 5;            // 0..7
    const int bCol = (tid & 31) << 2;     // 0..124
    const int tr = (tid >> 4) << 3;       // 0..120
    const int tc = (tid & 15) << 3;       // 0..120

    float acc[8][8];
    #pragma unroll
    for (int i = 0; i < 8; ++i)
        #pragma unroll
        for (int j = 0; j < 8; ++j) acc[i][j] = 0.f;

    const float* Ab = A + (size_t)(m0 + aRow) * K + aCol;
    const float* Bb = Bm + (size_t)bRow * N + n0 + bCol;

    for (int k0 = 0; k0 < K; k0 += 8) {
        float4 a4 = *(const float4*)(Ab + k0);
        As[aCol+0][aRow] = a4.x;
        As[aCol+1][aRow] = a4.y;
        As[aCol+2][aRow] = a4.z;
        As[aCol+3][aRow] = a4.w;
        *(float4*)(&Bs[bRow][bCol]) = *(const float4*)(Bb + (size_t)k0 * N);
        __syncthreads();
        #pragma unroll
        for (int k = 0; k < 8; ++k) {
            float4 a0 = *(const float4*)(&As[k][tr]);
            float4 a1 = *(const float4*)(&As[k][tr+4]);
            float4 b0 = *(const float4*)(&Bs[k][tc]);
            float4 b1 = *(const float4*)(&Bs[k][tc+4]);
            float ar[8] = {a0.x,a0.y,a0.z,a0.w,a1.x,a1.y,a1.z,a1.w};
            float br[8] = {b0.x,b0.y,b0.z,b0.w,b1.x,b1.y,b1.z,b1.w};
            #pragma unroll
            for (int i = 0; i < 8; ++i)
                #pragma unroll
                for (int j = 0; j < 8; ++j)
                    acc[i][j] += ar[i] * br[j];
        }
        __syncthreads();
    }

    #pragma unroll
    for (int i = 0; i < 8; ++i) {
        int m = m0 + tr + i;
        #pragma unroll
        for (int j = 0; j < 8; ++j) {
            int n = n0 + tc + j;
            float v = acc[i][j] + bias[n];
            if (MODE == 1) v = v * v;
            if (MODE == 0) {
                C[(size_t)m * N + n] = v;
            } else {
                int b = m >> 12, t = m & (NT-1);
                int h = n >> 6, e = n & 63;
                C[(((size_t)(b*NH + h))*NT + t)*NE + e] = v;
            }
        }
    }
}

// ---------------- kv_sum & k_sum: per (b,h), split over T -------------------
__global__ __launch_bounds__(256) void kvsum_partial(
    const float* __restrict__ kh2, const float* __restrict__ vh,
    float* __restrict__ kvp, float* __restrict__ ksp)
{
    int bh = blockIdx.x;
    int sp = blockIdx.y;
    const float* kb = kh2 + ((size_t)bh*NT + (size_t)sp*TCH)*NE;
    const float* vb = vh  + ((size_t)bh*NT + (size_t)sp*TCH)*NE;
    __shared__ float sk[16][NE];
    __shared__ float sv[16][NE];
    int tid = threadIdx.x;
    int d  = tid >> 2;           // 0..63
    int e0 = (tid & 3) << 4;     // 0,16,32,48
    float acc[16];
    #pragma unroll
    for (int j = 0; j < 16; ++j) acc[j] = 0.f;
    float ksacc = 0.f;

    for (int t0 = 0; t0 < TCH; t0 += 16) {
        #pragma unroll
        for (int i = 0; i < 4; ++i) {
            int idx = tid + i*256;
            ((float*)sk)[idx] = kb[(size_t)t0*NE + idx];
            ((float*)sv)[idx] = vb[(size_t)t0*NE + idx];
        }
        __syncthreads();
        #pragma unroll
        for (int tt = 0; tt < 16; ++tt) {
            float kval = sk[tt][d];
            ksacc += kval;
            #pragma unroll
            for (int j = 0; j < 16; ++j)
                acc[j] += kval * sv[tt][e0 + j];
        }
        __syncthreads();
    }
    float* outp = kvp + ((size_t)(bh*SPLIT + sp))*NE*NE + (size_t)d*NE + e0;
    #pragma unroll
    for (int j = 0; j < 16; ++j) outp[j] = acc[j];
    if ((tid & 3) == 0) ksp[(size_t)(bh*SPLIT + sp)*NE + d] = ksacc;
}

__global__ void kvsum_reduce(const float* __restrict__ kvp, const float* __restrict__ ksp,
                             float* __restrict__ kvs, float* __restrict__ kss)
{
    int bh = blockIdx.x;
    int tid = threadIdx.x; // 256
    for (int i = tid; i < NE*NE; i += 256) {
        float s = 0.f;
        #pragma unroll
        for (int sp = 0; sp < SPLIT; ++sp)
            s += kvp[((size_t)(bh*SPLIT + sp))*NE*NE + i];
        kvs[(size_t)bh*NE*NE + i] = s;
    }
    if (tid < NE) {
        float s = 0.f;
        #pragma unroll
        for (int sp = 0; sp < SPLIT; ++sp)
            s += ksp[(size_t)(bh*SPLIT + sp)*NE + tid];
        kss[(size_t)bh*NE + tid] = s;
    }
}

// ---------------- attn = z * (qh2 @ kv_sum), written to [b,t,(h,e)] ---------
__global__ __launch_bounds__(256) void attn_kernel(
    const float* __restrict__ qh2, const float* __restrict__ kvs,
    const float* __restrict__ kss, float* __restrict__ attn)
{
    int bh = blockIdx.y;   // 64
    int tt = blockIdx.x;   // 32 tiles of 128 t
    __shared__ float skv[NE][NE];
    __shared__ float sks[NE];
    int tid = threadIdx.x;
    for (int i = tid; i < NE*NE; i += 256)
        ((float*)skv)[i] = kvs[(size_t)bh*NE*NE + i];
    if (tid < NE) sks[tid] = kss[(size_t)bh*NE + tid];
    __syncthreads();

    int tl = tid >> 1;             // 0..127
    int e0 = (tid & 1) * 32;       // 0 or 32
    int t  = tt*128 + tl;
    const float* qrowp = qh2 + ((size_t)bh*NT + t)*NE;
    float qrow[NE];
    #pragma unroll
    for (int i = 0; i < 16; ++i) {
        float4 v = *(const float4*)(qrowp + i*4);
        qrow[i*4+0] = v.x; qrow[i*4+1] = v.y; qrow[i*4+2] = v.z; qrow[i*4+3] = v.w;
    }
    float zden = 1e-6f;
    #pragma unroll
    for (int d = 0; d < NE; ++d) zden += qrow[d] * sks[d];
    float z = 1.0f / zden;

    float acc[32];
    #pragma unroll
    for (int j = 0; j < 32; ++j) acc[j] = 0.f;
    #pragma unroll 4
    for (int d = 0; d < NE; ++d) {
        float qv = qrow[d];
        #pragma unroll
        for (int j = 0; j < 32; ++j)
            acc[j] += qv * skv[d][e0 + j];
    }
    int b = bh >> 4, h = bh & 15;
    float* op = attn + ((size_t)(b*NT + t))*ND + h*NE + e0;
    #pragma unroll
    for (int j = 0; j < 32; ++j) op[j] = acc[j] * z;
}

// ---------------- launch ----------------------------------------------------
extern "C" void kernel_launch(void* const* d_in, const int* in_sizes, int n_in,
                              void* d_out, int out_size)
{
    const float* q  = (const float*)d_in[0];
    const float* kv = (const float*)d_in[1];
    const float* Wq = (const float*)d_in[2];
    const float* bq = (const float*)d_in[3];
    const float* Wk = (const float*)d_in[4];
    const float* bk = (const float*)d_in[5];
    const float* Wv = (const float*)d_in[6];
    const float* bv = (const float*)d_in[7];
    const float* Wo = (const float*)d_in[8];
    const float* bo = (const float*)d_in[9];
    float* out = (float*)d_out;

    float *p_Wt, *p_Wot, *p_feat, *p_attn, *p_kvp, *p_ksp, *p_kvs, *p_kss;
    cudaGetSymbolAddress((void**)&p_Wt,   g_Wt);
    cudaGetSymbolAddress((void**)&p_Wot,  g_Wot);
    cudaGetSymbolAddress((void**)&p_feat, g_feat);
    cudaGetSymbolAddress((void**)&p_attn, g_attn);
    cudaGetSymbolAddress((void**)&p_kvp,  g_kvpart);
    cudaGetSymbolAddress((void**)&p_ksp,  g_kspart);
    cudaGetSymbolAddress((void**)&p_kvs,  g_kvsum);
    cudaGetSymbolAddress((void**)&p_kss,  g_ksum);

    float* wtq = p_Wt + 0*(size_t)ND*ND;
    float* wtk = p_Wt + 1*(size_t)ND*ND;
    float* wtv = p_Wt + 2*(size_t)ND*ND;
    float* fq  = p_feat + 0*(size_t)NBH*NT*NE;
    float* fk  = p_feat + 1*(size_t)NBH*NT*NE;
    float* fv  = p_feat + 2*(size_t)NBH*NT*NE;

    // 1) transpose weights into [K][N]
    {
        int n = ND*ND, thr = 256, blk = (n + thr - 1) / thr;
        transpose_proj_w<<<blk, thr>>>(Wq, wtq);
        transpose_proj_w<<<blk, thr>>>(Wk, wtk);
        transpose_proj_w<<<blk, thr>>>(Wv, wtv);
        transpose_wo<<<blk, thr>>>(Wo, p_Wot);
    }

    // 2) projections -> features [b,h,t,e] (squared for q,k)
    {
        dim3 grid(ND/128, NM/128);
        sgemm128<1><<<grid, 256>>>(q,  wtq, bq, fq, NM, ND, ND);
        sgemm128<1><<<grid, 256>>>(kv, wtk, bk, fk, NM, ND, ND);
        sgemm128<2><<<grid, 256>>>(kv, wtv, bv, fv, NM, ND, ND);
    }

    // 3) kv_sum and k_sum (deterministic split reduction)
    {
        dim3 grid(NBH, SPLIT);
        kvsum_partial<<<grid, 256>>>(fk, fv, p_kvp, p_ksp);
        kvsum_reduce<<<NBH, 256>>>(p_kvp, p_ksp, p_kvs, p_kss);
    }

    // 4) attn = z * qh2 @ kv_sum, layout [b,t,(h,e)]
    {
        dim3 grid(NT/128, NBH);
        attn_kernel<<<grid, 256>>>(fq, p_kvs, p_kss, p_attn);
    }

    // 5) out = attn @ Wo^T + bo
    {
        dim3 grid(ND/128, NM/128);
        sgemm128<0><<<grid, 256>>>(p_attn, p_Wot, bo, out, NM, ND, ND);
    }
}

// round 3
// speedup vs baseline: 2.7010x; 2.7010x over previous
#include <cuda_runtime.h>
#include <cuda_bf16.h>
#include <cstdint>
#include <cstddef>

// ---------------- problem constants ----------------
#define NB 4
#define NT 4096
#define ND 1024
#define NH 16
#define NE 64
#define NBH (NB*NH)     // 64
#define NM (NB*NT)      // 16384
#define K3 3072         // tripled K for bf16x3 split
#define SPLITR 8
#define TCH (NT/SPLITR) // 512

// ---------------- GEMM tiling ----------------
#define BM 128
#define BN 128
#define BKC 64
#define NCH (K3/BKC)                // 48
#define TILE_BYTES (BM*BKC*2)       // 16384
#define STAGE_BYTES (2*TILE_BYTES)  // 32768
#define STAGES 3
#define GEMM_SMEM (STAGES*STAGE_BYTES)  // 98304

// ---------------- scratch (device globals) ----------------
__device__ unsigned short g_Aq[(size_t)NM*K3];   // [qhi | qlo | qhi]
__device__ unsigned short g_Akv[(size_t)NM*K3];  // [kvhi | kvlo | kvhi]
__device__ unsigned short g_Aa[(size_t)NM*K3];   // attn [hi | lo | hi]
__device__ unsigned short g_Bw[4][(size_t)ND*K3]; // Wq,Wk,Wv,Wo as [n][hi|hi|lo]
__device__ float g_feat[3][(size_t)NBH*NT*NE];   // qh2, kh2, vh in [b,h,t,e]
__device__ float g_kvpart[(size_t)NBH*SPLITR*NE*NE];
__device__ float g_kspart[(size_t)NBH*SPLITR*NE];
__device__ float g_kvsum[(size_t)NBH*NE*NE];
__device__ float g_ksum[(size_t)NBH*NE];

// ---------------- helpers ----------------
__device__ __forceinline__ uint32_t s2u(const void* p) {
    uint32_t a;
    asm("{ .reg .u64 t; cvta.to.shared.u64 t, %1; cvt.u32.u64 %0, t; }" : "=r"(a) : "l"(p));
    return a;
}
__device__ __forceinline__ uint32_t swz(uint32_t b) { return b ^ ((b >> 3) & 0x70); }

__device__ __forceinline__ void cpasync16(uint32_t dst, const void* src) {
    asm volatile("cp.async.cg.shared.global [%0], [%1], 16;" :: "r"(dst), "l"(src));
}
__device__ __forceinline__ void cp_commit() {
    asm volatile("cp.async.commit_group;" ::: "memory");
}
template<int N>
__device__ __forceinline__ void cp_wait() {
    asm volatile("cp.async.wait_group %0;" :: "n"(N) : "memory");
}
__device__ __forceinline__ void ldsm4(uint32_t* r, uint32_t addr) {
    asm volatile("ldmatrix.sync.aligned.m8n8.x4.shared.b16 {%0,%1,%2,%3}, [%4];"
                 : "=r"(r[0]), "=r"(r[1]), "=r"(r[2]), "=r"(r[3]) : "r"(addr));
}
__device__ __forceinline__ void mma16816(float* c, const uint32_t* a, const uint32_t* b) {
    asm volatile(
        "mma.sync.aligned.m16n8k16.row.col.f32.bf16.bf16.f32 "
        "{%0,%1,%2,%3}, {%4,%5,%6,%7}, {%8,%9}, {%0,%1,%2,%3};"
        : "+f"(c[0]), "+f"(c[1]), "+f"(c[2]), "+f"(c[3])
        : "r"(a[0]), "r"(a[1]), "r"(a[2]), "r"(a[3]), "r"(b[0]), "r"(b[1]));
}

__device__ __forceinline__ void split1(float v, unsigned short& h, unsigned short& l) {
    __nv_bfloat16 bh = __float2bfloat16(v);
    float r = v - __bfloat162float(bh);
    h = __bfloat16_as_ushort(bh);
    l = __bfloat16_as_ushort(__float2bfloat16(r));
}

// ---------------- split kernels (fp32 -> bf16x3 trip layout) ----------------
// activations: A'[m] = [hi(0:1024) | lo(1024:2048) | hi(2048:3072)]
__global__ void split_act(const float4* __restrict__ x, unsigned short* __restrict__ A) {
    int gi = blockIdx.x * blockDim.x + threadIdx.x;  // over NM*ND/4
    if (gi >= NM*ND/4) return;
    int m = gi >> 8;             // 256 float4 per row
    int kq = (gi & 255) << 2;
    float4 v = x[gi];
    ushort4 h, l;
    split1(v.x, h.x, l.x); split1(v.y, h.y, l.y);
    split1(v.z, h.z, l.z); split1(v.w, h.w, l.w);
    unsigned short* row = A + (size_t)m * K3;
    *(ushort4*)(row + kq)        = h;
    *(ushort4*)(row + 1024 + kq) = l;
    *(ushort4*)(row + 2048 + kq) = h;
}
// proj weights W[h][k][e] -> B'[n=h*64+e] = [hi | hi | lo]
__global__ void wprep_proj(const float* __restrict__ W, unsigned short* __restrict__ B) {
    int idx = blockIdx.x * blockDim.x + threadIdx.x;
    if (idx >= ND*ND) return;
    int n = idx >> 10, k = idx & 1023;
    float v = W[((size_t)(n >> 6) * ND + k) * NE + (n & 63)];
    unsigned short h, l;
    split1(v, h, l);
    unsigned short* row = B + (size_t)n * K3;
    row[k] = h; row[1024 + k] = h; row[2048 + k] = l;
}
// Wo already [n][k]
__global__ void wprep_o(const float* __restrict__ W, unsigned short* __restrict__ B) {
    int idx = blockIdx.x * blockDim.x + threadIdx.x;
    if (idx >= ND*ND) return;
    int n = idx >> 10, k = idx & 1023;
    unsigned short h, l;
    split1(W[idx], h, l);
    unsigned short* row = B + (size_t)n * K3;
    row[k] = h; row[1024 + k] = h; row[2048 + k] = l;
}

// ---------------- bf16 MMA GEMM: C[M,N] = A'[M,K3] x B'[N,K3]^T + bias ------
// MODE 0: plain fp32 row-major C
// MODE 1: C -> feat [b,h,t,e] with square epilogue
// MODE 2: C -> feat [b,h,t,e] plain
template<int MODE>
__global__ void __launch_bounds__(256, 2) gemm_mma(
    const unsigned short* __restrict__ A, const unsigned short* __restrict__ Bm,
    const float* __restrict__ bias, float* __restrict__ C)
{
    extern __shared__ __align__(128) char smem[];
    const uint32_t sb = s2u(smem);
    const int tid = threadIdx.x, lane = tid & 31, wid = tid >> 5;
    const int m0 = blockIdx.y * BM, n0 = blockIdx.x * BN;
    const int mw = (wid >> 2) * 64;   // warp M offset (2 warps in M)
    const int nw = (wid & 3) * 32;    // warp N offset (4 warps in N)

    // per-thread load slots: 8 chunks of 16B per 128B row
    const int lrow = tid >> 3;        // 0..31 base row (advance by 32)
    const int lkc  = tid & 7;         // 16B chunk in row

    float acc[4][4][4];
    #pragma unroll
    for (int i = 0; i < 4; ++i)
        #pragma unroll
        for (int j = 0; j < 4; ++j)
            #pragma unroll
            for (int r = 0; r < 4; ++r) acc[i][j][r] = 0.f;

    // prologue: load chunks 0..STAGES-1
    #pragma unroll
    for (int s = 0; s < STAGES; ++s) {
        uint32_t sA = sb + s * STAGE_BYTES;
        uint32_t sB = sA + TILE_BYTES;
        int k0 = s * BKC;
        #pragma unroll
        for (int i = 0; i < 4; ++i) {
            int row = lrow + i * 32;
            uint32_t so = swz(row * 128 + lkc * 16);
            cpasync16(sA + so, A  + (size_t)(m0 + row) * K3 + k0 + lkc * 8);
            cpasync16(sB + so, Bm + (size_t)(n0 + row) * K3 + k0 + lkc * 8);
        }
        cp_commit();
    }

    for (int ch = 0; ch < NCH; ++ch) {
        cp_wait<STAGES - 1>();
        __syncthreads();
        const int s = ch % STAGES;
        const uint32_t aBase = sb + s * STAGE_BYTES;
        const uint32_t bBase = aBase + TILE_BYTES;

        const int arow = mw + (lane & 15);
        const int brow = nw + (lane & 7) + ((lane >> 4) & 1) * 8;
        #pragma unroll
        for (int k16 = 0; k16 < 4; ++k16) {
            uint32_t a[4][4], bf[2][4];
            const int acol = (k16 * 16 + (lane >> 4) * 8) * 2;
            const int bcol = (k16 * 16 + ((lane >> 3) & 1) * 8) * 2;
            #pragma unroll
            for (int mi = 0; mi < 4; ++mi)
                ldsm4(a[mi], aBase + swz((arow + mi * 16) * 128 + acol));
            #pragma unroll
            for (int nj = 0; nj < 2; ++nj)
                ldsm4(bf[nj], bBase + swz((brow + nj * 16) * 128 + bcol));
            #pragma unroll
            for (int mi = 0; mi < 4; ++mi)
                #pragma unroll
                for (int n8 = 0; n8 < 4; ++n8)
                    mma16816(acc[mi][n8], a[mi], &bf[n8 >> 1][(n8 & 1) * 2]);
        }
        __syncthreads();
        if (ch + STAGES < NCH) {
            uint32_t sA = aBase;
            uint32_t sB = aBase + TILE_BYTES;
            int k0 = (ch + STAGES) * BKC;
            #pragma unroll
            for (int i = 0; i < 4; ++i) {
                int row = lrow + i * 32;
                uint32_t so = swz(row * 128 + lkc * 16);
                cpasync16(sA + so, A  + (size_t)(m0 + row) * K3 + k0 + lkc * 8);
                cpasync16(sB + so, Bm + (size_t)(n0 + row) * K3 + k0 + lkc * 8);
            }
        }
        cp_commit();
    }

    // epilogue
    const int g = lane >> 2, t2 = (lane & 3) * 2;
    #pragma unroll
    for (int mi = 0; mi < 4; ++mi) {
        #pragma unroll
        for (int n8 = 0; n8 < 4; ++n8) {
            int col = n0 + nw + n8 * 8 + t2;
            float b0 = bias[col], b1 = bias[col + 1];
            int r0 = m0 + mw + mi * 16 + g;
            int r1 = r0 + 8;
            float2 v0 = make_float2(acc[mi][n8][0] + b0, acc[mi][n8][1] + b1);
            float2 v1 = make_float2(acc[mi][n8][2] + b0, acc[mi][n8][3] + b1);
            if (MODE == 1) {
                v0.x *= v0.x; v0.y *= v0.y; v1.x *= v1.x; v1.y *= v1.y;
            }
            if (MODE == 0) {
                *(float2*)(C + (size_t)r0 * ND + col) = v0;
                *(float2*)(C + (size_t)r1 * ND + col) = v1;
            } else {
                int h = col >> 6, e = col & 63;
                int b_0 = r0 >> 12, t_0 = r0 & (NT - 1);
                int b_1 = r1 >> 12, t_1 = r1 & (NT - 1);
                *(float2*)(C + ((((size_t)b_0 * NH + h) * NT + t_0) * NE + e)) = v0;
                *(float2*)(C + ((((size_t)b_1 * NH + h) * NT + t_1) * NE + e)) = v1;
            }
        }
    }
}

// ---------------- kv_sum & k_sum ----------------
__global__ __launch_bounds__(256) void kvsum_partial(
    const float* __restrict__ kh2, const float* __restrict__ vh,
    float* __restrict__ kvp, float* __restrict__ ksp)
{
    int bh = blockIdx.x;
    int sp = blockIdx.y;
    const float* kb = kh2 + ((size_t)bh*NT + (size_t)sp*TCH)*NE;
    const float* vb = vh  + ((size_t)bh*NT + (size_t)sp*TCH)*NE;
    __shared__ float sk[16][NE];
    __shared__ float sv[16][NE];
    int tid = threadIdx.x;
    int d  = tid >> 2;
    int e0 = (tid & 3) << 4;
    float acc[16];
    #pragma unroll
    for (int j = 0; j < 16; ++j) acc[j] = 0.f;
    float ksacc = 0.f;

    for (int t0 = 0; t0 < TCH; t0 += 16) {
        #pragma unroll
        for (int i = 0; i < 4; ++i) {
            int idx = tid + i*256;
            ((float*)sk)[idx] = kb[(size_t)t0*NE + idx];
            ((float*)sv)[idx] = vb[(size_t)t0*NE + idx];
        }
        __syncthreads();
        #pragma unroll
        for (int tt = 0; tt < 16; ++tt) {
            float kval = sk[tt][d];
            ksacc += kval;
            #pragma unroll
            for (int j = 0; j < 16; ++j)
                acc[j] += kval * sv[tt][e0 + j];
        }
        __syncthreads();
    }
    float* outp = kvp + ((size_t)(bh*SPLITR + sp))*NE*NE + (size_t)d*NE + e0;
    #pragma unroll
    for (int j = 0; j < 16; ++j) outp[j] = acc[j];
    if ((tid & 3) == 0) ksp[(size_t)(bh*SPLITR + sp)*NE + d] = ksacc;
}

__global__ void kvsum_reduce(const float* __restrict__ kvp, const float* __restrict__ ksp,
                             float* __restrict__ kvs, float* __restrict__ kss)
{
    int bh = blockIdx.x;
    int tid = threadIdx.x;
    for (int i = tid; i < NE*NE; i += 256) {
        float s = 0.f;
        #pragma unroll
        for (int sp = 0; sp < SPLITR; ++sp)
            s += kvp[((size_t)(bh*SPLITR + sp))*NE*NE + i];
        kvs[(size_t)bh*NE*NE + i] = s;
    }
    if (tid < NE) {
        float s = 0.f;
        #pragma unroll
        for (int sp = 0; sp < SPLITR; ++sp)
            s += ksp[(size_t)(bh*SPLITR + sp)*NE + tid];
        kss[(size_t)bh*NE + tid] = s;
    }
}

// ---------------- attn = z * (qh2 @ kv_sum) -> bf16x3 trip layout -----------
__global__ __launch_bounds__(256) void attn_kernel(
    const float* __restrict__ qh2, const float* __restrict__ kvs,
    const float* __restrict__ kss, unsigned short* __restrict__ Aout)
{
    int bh = blockIdx.y;
    int tt = blockIdx.x;
    __shared__ float skv[NE][NE];
    __shared__ float sks[NE];
    int tid = threadIdx.x;
    for (int i = tid; i < NE*NE; i += 256)
        ((float*)skv)[i] = kvs[(size_t)bh*NE*NE + i];
    if (tid < NE) sks[tid] = kss[(size_t)bh*NE + tid];
    __syncthreads();

    int tl = tid >> 1;
    int e0 = (tid & 1) * 32;
    int t  = tt*128 + tl;
    const float* qrowp = qh2 + ((size_t)bh*NT + t)*NE;
    float qrow[NE];
    #pragma unroll
    for (int i = 0; i < 16; ++i) {
        float4 v = *(const float4*)(qrowp + i*4);
        qrow[i*4+0] = v.x; qrow[i*4+1] = v.y; qrow[i*4+2] = v.z; qrow[i*4+3] = v.w;
    }
    float zden = 1e-6f;
    #pragma unroll
    for (int d = 0; d < NE; ++d) zden += qrow[d] * sks[d];
    float z = 1.0f / zden;

    float acc[32];
    #pragma unroll
    for (int j = 0; j < 32; ++j) acc[j] = 0.f;
    #pragma unroll 4
    for (int d = 0; d < NE; ++d) {
        float qv = qrow[d];
        #pragma unroll
        for (int j = 0; j < 32; ++j)
            acc[j] += qv * skv[d][e0 + j];
    }
    int b = bh >> 4, h = bh & 15;
    int m = b * NT + t;
    size_t base = (size_t)m * K3 + h * NE + e0;
    #pragma unroll
    for (int j = 0; j < 32; j += 2) {
        float va = acc[j] * z, vb = acc[j+1] * z;
        unsigned short h0, l0, h1, l1;
        split1(va, h0, l0);
        split1(vb, h1, l1);
        ushort2 hh = make_ushort2(h0, h1);
        ushort2 ll = make_ushort2(l0, l1);
        *(ushort2*)(Aout + base + j)        = hh;
        *(ushort2*)(Aout + base + 1024 + j) = ll;
        *(ushort2*)(Aout + base + 2048 + j) = hh;
    }
}

// ---------------- launch ----------------
extern "C" void kernel_launch(void* const* d_in, const int* in_sizes, int n_in,
                              void* d_out, int out_size)
{
    const float* q  = (const float*)d_in[0];
    const float* kv = (const float*)d_in[1];
    const float* Wq = (const float*)d_in[2];
    const float* bq = (const float*)d_in[3];
    const float* Wk = (const float*)d_in[4];
    const float* bk = (const float*)d_in[5];
    const float* Wv = (const float*)d_in[6];
    const float* bv = (const float*)d_in[7];
    const float* Wo = (const float*)d_in[8];
    const float* bo = (const float*)d_in[9];
    float* out = (float*)d_out;

    unsigned short *Aq, *Akv, *Aa, *Bw;
    float *feat, *kvp, *ksp, *kvs, *kss;
    cudaGetSymbolAddress((void**)&Aq,  g_Aq);
    cudaGetSymbolAddress((void**)&Akv, g_Akv);
    cudaGetSymbolAddress((void**)&Aa,  g_Aa);
    cudaGetSymbolAddress((void**)&Bw,  g_Bw);
    cudaGetSymbolAddress((void**)&feat, g_feat);
    cudaGetSymbolAddress((void**)&kvp, g_kvpart);
    cudaGetSymbolAddress((void**)&ksp, g_kspart);
    cudaGetSymbolAddress((void**)&kvs, g_kvsum);
    cudaGetSymbolAddress((void**)&kss, g_ksum);

    unsigned short* Bq = Bw + 0*(size_t)ND*K3;
    unsigned short* Bk = Bw + 1*(size_t)ND*K3;
    unsigned short* Bv = Bw + 2*(size_t)ND*K3;
    unsigned short* Bo = Bw + 3*(size_t)ND*K3;
    float* fq = feat + 0*(size_t)NBH*NT*NE;
    float* fk = feat + 1*(size_t)NBH*NT*NE;
    float* fv = feat + 2*(size_t)NBH*NT*NE;

    cudaFuncSetAttribute((const void*)gemm_mma<0>, cudaFuncAttributeMaxDynamicSharedMemorySize, GEMM_SMEM);
    cudaFuncSetAttribute((const void*)gemm_mma<1>, cudaFuncAttributeMaxDynamicSharedMemorySize, GEMM_SMEM);
    cudaFuncSetAttribute((const void*)gemm_mma<2>, cudaFuncAttributeMaxDynamicSharedMemorySize, GEMM_SMEM);

    // 1) splits
    {
        int n4 = NM*ND/4;
        int blk = (n4 + 255) / 256;
        split_act<<<blk, 256>>>((const float4*)q,  Aq);
        split_act<<<blk, 256>>>((const float4*)kv, Akv);
        int blk2 = (ND*ND + 255) / 256;
        wprep_proj<<<blk2, 256>>>(Wq, Bq);
        wprep_proj<<<blk2, 256>>>(Wk, Bk);
        wprep_proj<<<blk2, 256>>>(Wv, Bv);
        wprep_o<<<blk2, 256>>>(Wo, Bo);
    }
    // 2) projection GEMMs
    {
        dim3 grid(ND / BN, NM / BM);
        gemm_mma<1><<<grid, 256, GEMM_SMEM>>>(Aq,  Bq, bq, fq);
        gemm_mma<1><<<grid, 256, GEMM_SMEM>>>(Akv, Bk, bk, fk);
        gemm_mma<2><<<grid, 256, GEMM_SMEM>>>(Akv, Bv, bv, fv);
    }
    // 3) kv_sum / k_sum
    {
        dim3 grid(NBH, SPLITR);
        kvsum_partial<<<grid, 256>>>(fk, fv, kvp, ksp);
        kvsum_reduce<<<NBH, 256>>>(kvp, ksp, kvs, kss);
    }
    // 4) attn (emits bf16x3 trip layout)
    {
        dim3 grid(NT / 128, NBH);
        attn_kernel<<<grid, 256>>>(fq, kvs, kss, Aa);
    }
    // 5) output GEMM
    {
        dim3 grid(ND / BN, NM / BM);
        gemm_mma<0><<<grid, 256, GEMM_SMEM>>>(Aa, Bo, bo, out);
    }
}